// round 12
// baseline (speedup 1.0000x reference)
#include <cuda_runtime.h>
#include <cstdint>

// Bayer mosaic channel select — FINAL (converged at the traffic floor).
//   out[b,i,j] = img[b, c, i, j]
//   c = 1 if (i+j) even; else 2 if i even; else 0
// Row-parity view:
//   i even: j even -> ch1, j odd -> ch2
//   i odd : j even -> ch0, j odd -> ch1
//
// Traffic floor: 384 MB (ch1 reads 128 MB + ch0/ch2 64 MB each — both
// j-parities span every 32B sector, so nothing can be elided — + 128 MB
// write). Best ncu across 11 rounds: 53.6 us at 83.6% DRAM = at the floor.
//
// Configuration (each element measured best-in-class):
//   - Blackwell 256-bit global accesses (ld/st.global.v8.f32): one 32B
//     sector per instruction; halved LDG/STG count (ncu 55.9 -> 54.1)
//   - row-pair CTA, 512 threads: merges the ch1 reads of rows (i, i+1)
//     into one 16 KB contiguous extent + 16 KB contiguous write
//     (ncu 54.1 -> 53.6); 512-thread blocks keep occupancy granularity
//   - per thread: 2x LDG.256 + 1x STG.256, pure 32-bit shift/add indexing
// Measured regressions (do not reintroduce): __ldcs/__stcs hints, adjacent
// per-thread load batching, persistent grid-stride, 1024-thread blocks.

static constexpr unsigned H = 2048;
static constexpr unsigned W = 2048;
static constexpr unsigned PLANE = H * W;         // 4,194,304 elements
static constexpr unsigned W8 = W / 8;            // 256 sectors per row

struct __align__(32) f8 { float v[8]; };

__device__ __forceinline__ f8 ldg256(const float* p) {
    f8 r;
    asm volatile("ld.global.v8.f32 {%0,%1,%2,%3,%4,%5,%6,%7}, [%8];"
                 : "=f"(r.v[0]), "=f"(r.v[1]), "=f"(r.v[2]), "=f"(r.v[3]),
                   "=f"(r.v[4]), "=f"(r.v[5]), "=f"(r.v[6]), "=f"(r.v[7])
                 : "l"(p));
    return r;
}

__device__ __forceinline__ void stg256(float* p, const f8& r) {
    asm volatile("st.global.v8.f32 [%0], {%1,%2,%3,%4,%5,%6,%7,%8};"
                 :: "l"(p),
                    "f"(r.v[0]), "f"(r.v[1]), "f"(r.v[2]), "f"(r.v[3]),
                    "f"(r.v[4]), "f"(r.v[5]), "f"(r.v[6]), "f"(r.v[7])
                 : "memory");
}

__global__ __launch_bounds__(512)
void bayer_kernel(const float* __restrict__ img, float* __restrict__ out) {
    const unsigned t   = threadIdx.x;              // [0,512)
    const unsigned sub = t >> 8;                   // 0: even row of pair, 1: odd
    const unsigned j   = (t & (W8 - 1u)) << 3;     // element index within row
    const unsigned i   = (blockIdx.x << 1) | sub;  // actual row
    const unsigned b   = blockIdx.y;               // batch

    // cA serves even j (even row -> ch1, odd row -> ch0); cB = cA + 1 always.
    const unsigned cA = 1u - sub;
    const unsigned row_base = (b * 3u + cA) * PLANE + i * W + j;

    const f8 a  = ldg256(img + row_base);            // cA plane
    const f8 bv = ldg256(img + row_base + PLANE);    // cB plane

    f8 o;
    #pragma unroll
    for (int k = 0; k < 8; k += 2) {
        o.v[k]     = a.v[k];       // even j
        o.v[k + 1] = bv.v[k + 1];  // odd j
    }

    stg256(out + (b * H + i) * W + j, o);
}

extern "C" void kernel_launch(void* const* d_in, const int* in_sizes, int n_in,
                              void* d_out, int out_size) {
    const float* img = (const float*)d_in[0];
    float* out = (float*)d_out;

    dim3 grid(H / 2, 8);    // (1024 row-pairs, 8 batches) = 8192 CTAs of 512
    bayer_kernel<<<grid, 512>>>(img, out);
}

// round 13
// speedup vs baseline: 1.0083x; 1.0083x over previous
#include <cuda_runtime.h>
#include <cstdint>

// Bayer mosaic channel select — FINAL (converged at the traffic floor).
//   out[b,i,j] = img[b, c, i, j]
//   c = 1 if (i+j) even; else 2 if i even; else 0
// Row-parity view:
//   i even: j even -> ch1, j odd -> ch2
//   i odd : j even -> ch0, j odd -> ch1
//
// Traffic floor: 384 MB (ch1 reads 128 MB + ch0/ch2 64 MB each — both
// j-parities span every 32B sector of every needed row, so no read can be
// elided — plus 128 MB write). Best ncu: 53.0 us @ 84.4% DRAM / 6.69 TB/s
// = at the floor. Compute pipes <5%; no idle resource remains.
//
// Configuration (each element measured best-in-class over 12 rounds):
//   - Blackwell 256-bit global accesses (ld/st.global.v8.f32): one full
//     32B sector per instruction; halved LDG/STG count (ncu 55.9 -> 54.1)
//   - row-pair CTA, 512 threads: merges the ch1 reads of rows (i, i+1)
//     into one 16 KB contiguous extent + 16 KB contiguous write
//     (ncu 54.1 -> 53.0) while keeping occupancy granularity
//   - per thread: 2x LDG.256 + 1x STG.256, pure 32-bit shift/add indexing
// Measured regressions (do not reintroduce): __ldcs/__stcs hints, adjacent
// per-thread load batching, persistent grid-stride, 1024-thread blocks.

static constexpr unsigned H = 2048;
static constexpr unsigned W = 2048;
static constexpr unsigned PLANE = H * W;         // 4,194,304 elements
static constexpr unsigned W8 = W / 8;            // 256 sectors per row

struct __align__(32) f8 { float v[8]; };

__device__ __forceinline__ f8 ldg256(const float* p) {
    f8 r;
    asm volatile("ld.global.v8.f32 {%0,%1,%2,%3,%4,%5,%6,%7}, [%8];"
                 : "=f"(r.v[0]), "=f"(r.v[1]), "=f"(r.v[2]), "=f"(r.v[3]),
                   "=f"(r.v[4]), "=f"(r.v[5]), "=f"(r.v[6]), "=f"(r.v[7])
                 : "l"(p));
    return r;
}

__device__ __forceinline__ void stg256(float* p, const f8& r) {
    asm volatile("st.global.v8.f32 [%0], {%1,%2,%3,%4,%5,%6,%7,%8};"
                 :: "l"(p),
                    "f"(r.v[0]), "f"(r.v[1]), "f"(r.v[2]), "f"(r.v[3]),
                    "f"(r.v[4]), "f"(r.v[5]), "f"(r.v[6]), "f"(r.v[7])
                 : "memory");
}

__global__ __launch_bounds__(512)
void bayer_kernel(const float* __restrict__ img, float* __restrict__ out) {
    const unsigned t   = threadIdx.x;              // [0,512)
    const unsigned sub = t >> 8;                   // 0: even row of pair, 1: odd
    const unsigned j   = (t & (W8 - 1u)) << 3;     // element index within row
    const unsigned i   = (blockIdx.x << 1) | sub;  // actual row
    const unsigned b   = blockIdx.y;               // batch

    // cA serves even j (even row -> ch1, odd row -> ch0); cB = cA + 1 always.
    const unsigned cA = 1u - sub;
    const unsigned row_base = (b * 3u + cA) * PLANE + i * W + j;

    const f8 a  = ldg256(img + row_base);            // cA plane
    const f8 bv = ldg256(img + row_base + PLANE);    // cB plane

    f8 o;
    #pragma unroll
    for (int k = 0; k < 8; k += 2) {
        o.v[k]     = a.v[k];       // even j
        o.v[k + 1] = bv.v[k + 1];  // odd j
    }

    stg256(out + (b * H + i) * W + j, o);
}

extern "C" void kernel_launch(void* const* d_in, const int* in_sizes, int n_in,
                              void* d_out, int out_size) {
    const float* img = (const float*)d_in[0];
    float* out = (float*)d_out;

    dim3 grid(H / 2, 8);    // (1024 row-pairs, 8 batches) = 8192 CTAs of 512
    bayer_kernel<<<grid, 512>>>(img, out);
}